// round 14
// baseline (speedup 1.0000x reference)
#include <cuda_runtime.h>

#define BATCH 64
#define NUM_SPEC 8
#define VOCAB 128000
#define ROWS 512
#define HALVES 1024
#define HALF_F4 16000       // float4 per half-row
#define THREADS 160         // 5 warps; 16000/160 = 100 f4/thread
#define NWARPS (THREADS / 32)
#define FULL_BATCHES 12     // 12*8 = 96
#define TAIL 4              // +4 = 100

// Device scratch (no allocation allowed). Plain per-half stores (one CTA owns
// a half-row), overwritten every launch -> only the counter needs reset.
__device__ float g_val[HALVES];
__device__ int   g_idx[HALVES];
__device__ int   g_done;

// ---------------------------------------------------------------------------
// One CTA per half-row (1024 CTAs, single balanced wave at 12 CTAs/SM max):
// static front-batched streaming loads (MLP 8), strict-> first-occurrence
// argmax, warp+smem reduce, last-arriver fused epilogue.
// Output (float32):
//   [0 .. 576)   output_token_ids    [64][9]
//   [576 .. 640) num_rejected_tokens [64]
//   [640 .. 704) last_token_ids      [64]
// ---------------------------------------------------------------------------
__global__ void __launch_bounds__(THREADS, 12) fused_rejection_kernel(
    const float* __restrict__ logits,
    const int*   __restrict__ draft,    // [64][8]
    const int*   __restrict__ bonus,    // [64][1]
    float*       __restrict__ out)
{
    __shared__ float sv[NWARPS];
    __shared__ int   si[NWARPS];
    __shared__ int   s_last;

    const int cta  = blockIdx.x;        // 0..1023
    const int row  = cta >> 1;
    const int half = cta & 1;
    const float4* __restrict__ p =
        reinterpret_cast<const float4*>(logits + (size_t)row * VOCAB) +
        half * HALF_F4;

    float best = -3.402823466e+38f;
    int   bidx = 0;                     // index local to the half

    int base = threadIdx.x;
    #pragma unroll 1
    for (int m = 0; m < FULL_BATCHES; m++) {
        float4 v[8];
        #pragma unroll
        for (int k = 0; k < 8; k++) v[k] = __ldcs(&p[base + k * THREADS]);
        #pragma unroll
        for (int k = 0; k < 8; k++) {
            int e = (base + k * THREADS) * 4;
            if (v[k].x > best) { best = v[k].x; bidx = e; }
            if (v[k].y > best) { best = v[k].y; bidx = e + 1; }
            if (v[k].z > best) { best = v[k].z; bidx = e + 2; }
            if (v[k].w > best) { best = v[k].w; bidx = e + 3; }
        }
        base += 8 * THREADS;
    }
    {   // static tail: 4 front-batched f4 per thread
        float4 v[TAIL];
        #pragma unroll
        for (int k = 0; k < TAIL; k++) v[k] = __ldcs(&p[base + k * THREADS]);
        #pragma unroll
        for (int k = 0; k < TAIL; k++) {
            int e = (base + k * THREADS) * 4;
            if (v[k].x > best) { best = v[k].x; bidx = e; }
            if (v[k].y > best) { best = v[k].y; bidx = e + 1; }
            if (v[k].z > best) { best = v[k].z; bidx = e + 2; }
            if (v[k].w > best) { best = v[k].w; bidx = e + 3; }
        }
    }

    // Warp reduce, tie-break toward smaller index.
    #pragma unroll
    for (int off = 16; off > 0; off >>= 1) {
        float ov = __shfl_down_sync(0xffffffffu, best, off);
        int   oi = __shfl_down_sync(0xffffffffu, bidx, off);
        if (ov > best || (ov == best && oi < bidx)) { best = ov; bidx = oi; }
    }
    const int w = threadIdx.x >> 5;
    if ((threadIdx.x & 31) == 0) { sv[w] = best; si[w] = bidx; }
    __syncthreads();

    if (threadIdx.x == 0) {
        #pragma unroll
        for (int j = 1; j < NWARPS; j++) {
            if (sv[j] > best || (sv[j] == best && si[j] < bidx)) {
                best = sv[j]; bidx = si[j];
            }
        }
        g_val[cta] = best;
        g_idx[cta] = bidx + half * (HALF_F4 * 4);   // global vocab index
        __threadfence();
        s_last = (atomicAdd(&g_done, 1) == HALVES - 1);
    }
    __syncthreads();

    // Last-arriver CTA: epilogue with 64 parallel threads (one per batch).
    if (s_last) {
        __threadfence();                      // order reads after observed adds
        if (threadIdx.x == 0) g_done = 0;     // reset for next graph replay
        const int b = threadIdx.x;
        if (b < BATCH) {
            int tt[NUM_SPEC];
            #pragma unroll
            for (int j = 0; j < NUM_SPEC; j++) {
                const int r = b * NUM_SPEC + j;
                float v0 = __ldcg(&g_val[2 * r]);
                float v1 = __ldcg(&g_val[2 * r + 1]);
                int   i0 = __ldcg(&g_idx[2 * r]);
                int   i1 = __ldcg(&g_idx[2 * r + 1]);
                // half-0 indices are smaller: >= keeps first occurrence
                tt[j] = (v0 >= v1) ? i0 : i1;
            }

            int num_accept = 0;
            bool prefix = true;
            #pragma unroll
            for (int j = 0; j < NUM_SPEC; j++) {
                if (prefix) {
                    if (draft[b * NUM_SPEC + j] == tt[j]) num_accept++;
                    else prefix = false;
                }
            }
            const bool all_acc  = (num_accept == NUM_SPEC);
            const int  keep_cnt = all_acc ? NUM_SPEC : (num_accept + 1);
            const int  bon      = bonus[b];

            #pragma unroll
            for (int j = 0; j < NUM_SPEC; j++) {
                out[b * (NUM_SPEC + 1) + j] = (j < keep_cnt) ? (float)tt[j] : -1.0f;
            }
            out[b * (NUM_SPEC + 1) + NUM_SPEC] = all_acc ? (float)bon : -1.0f;
            out[BATCH * (NUM_SPEC + 1) + b]    = (float)(NUM_SPEC - num_accept);
            out[BATCH * (NUM_SPEC + 1) + BATCH + b] =
                all_acc ? (float)bon : (float)tt[num_accept];
        }
    }
}

extern "C" void kernel_launch(void* const* d_in, const int* in_sizes, int n_in,
                              void* d_out, int out_size)
{
    const float* logits = (const float*)d_in[0];
    const int*   draft  = (const int*)d_in[1];
    const int*   bonus  = (const int*)d_in[2];
    float*       out    = (float*)d_out;

    fused_rejection_kernel<<<HALVES, THREADS>>>(logits, draft, bonus, out);
}